// round 15
// baseline (speedup 1.0000x reference)
#include <cuda_runtime.h>
#include <math.h>

// Problem dims (fixed by reference: B=1024, L=256)
#define NRES   262144
#define TPB    256
#define NBLK   (NRES / TPB)    // 1024
#define NCHUNK (NRES / 128)    // 2048 chunks of 128 residues (2 threads each)
#define NPART  (NCHUNK * 8)    // per-(chunk,slice) partials
#define NCB    591             // compute blocks; block NCB is the dedicated reducer
#define PGRID  (NCB + 1)       // 592 = 148 SMs * 4 CTAs -> all resident
#define MAXPER 16              // max chunks per block in the schedule
#define BLEN   1.52f
#define PI_F   3.14159265358979323846f

// ---------------- small vec helpers ----------------
struct V3 { float x, y, z; };
__device__ __forceinline__ V3 v3(float a, float b, float c) { V3 r; r.x = a; r.y = b; r.z = c; return r; }
__device__ __forceinline__ V3 operator+(V3 a, V3 b) { return v3(a.x + b.x, a.y + b.y, a.z + b.z); }
__device__ __forceinline__ V3 operator-(V3 a, V3 b) { return v3(a.x - b.x, a.y - b.y, a.z - b.z); }
__device__ __forceinline__ V3 operator*(V3 a, float s) { return v3(a.x * s, a.y * s, a.z * s); }
__device__ __forceinline__ float dot3(V3 a, V3 b) { return a.x * b.x + a.y * b.y + a.z * b.z; }
__device__ __forceinline__ V3 crs3(V3 a, V3 b) {
    return v3(a.y * b.z - a.z * b.y, a.z * b.x - a.x * b.z, a.x * b.y - a.y * b.x);
}

// ---------------- residue-type tables ----------------
__constant__ int c_nsc[21]  = {1,7,4,4,2,5,5,0,6,4,4,5,4,7,3,2,3,10,8,3,0};
__constant__ int c_chin[21] = {0,4,2,2,1,3,3,0,2,2,2,4,3,2,2,1,1,2,2,1,0};

// ---------------- device state (static; no runtime alloc) ----------------
// chi(t) lives in buffer t % 3. Triple buffering makes depth-1 speculation safe:
// a speculative iteration st+1 writes buffer (st+2)%3, never the final st%3.
__device__ float  d_chi[3 * 4 * NRES];
__device__ float  d_m  [4 * NRES];
__device__ float  d_v  [4 * NRES];
__device__ float  d_pre[15 * NRES];      // SoA: p1, CB, u1, n1, m1
__device__ float  d_tgt[30 * NRES];      // SoA sidechain targets
__device__ int    d_nsc[NRES];
__device__ int    d_inv[NRES];           // original i -> sorted j
__device__ int    d_bhist[11 * NBLK];
__device__ double d_part[2 * NPART];     // per-(chunk,slice) loss partials, by parity
__device__ int    d_arr[2];              // arrival counters, by parity
__device__ int    d_gen, d_stopT, d_finalbuf, d_cnt, d_nstatic;
__device__ float  d_invden;
__device__ int    d_assign[NCHUNK];      // chunk -> compute block
__device__ int    d_scnt[NCB];           // per-block chunk counts
__device__ int    d_list[NCB * MAXPER];  // per-block chunk lists

__device__ __forceinline__ V3 ldpre(int c, int j) {
    return v3(d_pre[(3 * c + 0) * NRES + j], d_pre[(3 * c + 1) * NRES + j], d_pre[(3 * c + 2) * NRES + j]);
}
__device__ __forceinline__ void stpre(int c, int j, V3 a) {
    d_pre[(3 * c + 0) * NRES + j] = a.x;
    d_pre[(3 * c + 1) * NRES + j] = a.y;
    d_pre[(3 * c + 2) * NRES + j] = a.z;
}
__device__ __forceinline__ V3 ldtgt(int s, int j) {
    return v3(d_tgt[(3 * s + 0) * NRES + j], d_tgt[(3 * s + 1) * NRES + j], d_tgt[(3 * s + 2) * NRES + j]);
}

// NeRF extend, primal only
__device__ __forceinline__ V3 extendp(V3 a, V3 b, V3 c, float cT, float sT) {
    const float cA = cosf(1.937f), sA = sinf(1.937f);
    V3 v = c - b; float nv = sqrtf(dot3(v, v)); V3 u = v * (1.f / (nv + 1e-8f));
    V3 w = b - a; V3 pp = crs3(w, u); float np = sqrtf(dot3(pp, pp)); V3 nn = pp * (1.f / (np + 1e-8f));
    V3 mm = crs3(nn, u);
    return c + (u * (-cA) + (mm * cT + nn * sT) * sA) * BLEN;
}

__device__ __forceinline__ float dihed(V3 a, V3 b, V3 c, V3 d) {
    V3 b1 = b - a, b2 = c - b, b3 = d - c;
    V3 n1 = crs3(b1, b2), n2 = crs3(b2, b3);
    float nb = sqrtf(dot3(b2, b2));
    V3 u2 = b2 * (1.f / (nb + 1e-8f));
    V3 m1 = crs3(n1, u2);
    return atan2f(dot3(m1, n2), dot3(n1, n2));
}

// ---------------- counting sort by n_sc (deterministic / stable) ----------------
__global__ void k_hist(const int* __restrict__ S) {
    __shared__ int h[11];
    int tid = threadIdx.x;
    if (tid < 11) h[tid] = 0;
    __syncthreads();
    int i = blockIdx.x * TPB + tid;
    int nsc = c_nsc[S[i] % 21];
    atomicAdd(&h[nsc], 1);
    __syncthreads();
    if (tid < 11) d_bhist[tid * NBLK + blockIdx.x] = h[tid];
}

// scan + control-state init + chunk->block schedule (snake rows 0-2, LPT tail).
// 352 threads = 11 warps (one per nsc class).
__global__ void k_scan() {
    __shared__ int tot[11], base[11], cbase[12];
    __shared__ int W[NCHUNK];       // per-chunk relative cost
    __shared__ int load[NCB];
    __shared__ int nstat_s;
    const int tid = threadIdx.x;
    const int wv = tid >> 5, lane = tid & 31;

    int lsum = 0;
    if (wv < 11) {
        for (int j = 0; j < 32; j++) lsum += d_bhist[wv * NBLK + lane * 32 + j];
        int isum = lsum;
        for (int o = 1; o < 32; o <<= 1) {
            int t = __shfl_up_sync(0xffffffffu, isum, o);
            if (lane >= o) isum += t;
        }
        if (lane == 31) tot[wv] = isum;
    }
    __syncthreads();

    if (tid == 0) {
        int o = 0, cnt = 0;
        for (int u = 0; u < 11; u++) { base[u] = o; cbase[u] = o; o += tot[u]; cnt += u * tot[u]; }
        cbase[11] = NRES;
        d_cnt = cnt;
        d_invden = 1.0f / (3.0f * (float)cnt);
        d_gen = 0; d_stopT = -1; d_finalbuf = 0;
        d_arr[0] = 0; d_arr[1] = 0;
        int nst = (tot[0] + tot[1]) >> 7;   // chunks wholly of nsc<=1 residues
        d_nstatic = nst;
        nstat_s = nst;
    }
    __syncthreads();

    // rewrite d_bhist to per-block scatter offsets (warp-parallel prefix per class)
    if (wv < 11) {
        int excl = lsum;
        for (int o = 1; o < 32; o <<= 1) {
            int t = __shfl_up_sync(0xffffffffu, excl, o);
            if (lane >= o) excl += t;
        }
        excl -= lsum;   // exclusive
        int off = base[wv] + excl;
        for (int j = 0; j < 32; j++) {
            int idx = wv * NBLK + lane * 32 + j;
            int t = d_bhist[idx];
            d_bhist[idx] = off;
            off += t;
        }
    }

    // per-chunk cost: sum over the chunk's 8 slices of (4 + 3*chain_steps(slice-max class)).
    for (int c = tid; c < NCHUNK; c += 352) {
        int wsum = 0;
        for (int w = 0; w < 8; w++) {
            int j = (c << 7) + (w << 4) + 15;   // last (max-class) residue of this slice
            int u = 0;
            for (int q = 1; q < 11; q++) if (j >= cbase[q]) u = q;
            int steps = u > 2 ? (u - 2) : 0;
            wsum += 4 + 3 * steps;
        }
        if (c < nstat_s) wsum = 2;   // static chunk: skipped after it=0
        W[c] = wsum;
    }
    for (int c = tid; c < 3 * NCB; c += 352) {
        int r = c / NCB, col = c % NCB;
        d_assign[c] = (r & 1) ? (NCB - 1 - col) : col;
    }
    for (int b = tid; b < NCB; b += 352) d_scnt[b] = 0;
    __syncthreads();
    for (int b = tid; b < NCB; b += 352)
        load[b] = W[b] + W[2 * NCB - 1 - b] + W[2 * NCB + b];
    __syncthreads();

    // LPT greedy for the expensive tail chunks (descending cost order)
    if (wv == 0) {
        for (int c = NCHUNK - 1; c >= 3 * NCB; --c) {
            int best = 0x7fffffff;
            for (int b = lane; b < NCB; b += 32) {
                int v = load[b] * 1024 + b;     // tie-break: lowest block id
                if (v < best) best = v;
            }
#pragma unroll
            for (int o = 16; o; o >>= 1) {
                int t = __shfl_xor_sync(0xffffffffu, best, o);
                if (t < best) best = t;
            }
            int bmin = best & 1023;
            if (lane == 0) { load[bmin] += W[c]; d_assign[c] = bmin; }
            __syncwarp();
        }
    }
}

// materialize per-block chunk lists (order within block irrelevant: per-chunk
// partials and per-residue state are chunk-owned, nothing accumulates across chunks)
__global__ void k_sched() {
    int c = blockIdx.x * 256 + threadIdx.x;
    if (c < NCHUNK) {
        int a = d_assign[c];
        int pos = atomicAdd(&d_scnt[a], 1);
        d_list[a * MAXPER + pos] = c;
    }
}

// scatter + per-residue precompute, stored at sorted position j.
// All three chi buffers get the masked chi0 (dead chis therefore stay 0 in
// whichever buffer k_final reads). d_m/d_v not initialized: the it==0 fused
// Adam step uses m = 0.1f*g, v = (0.001f*g)*g (bitwise-equal to m=v=0 forms).
__global__ void k_scatter(const float* __restrict__ X, const int* __restrict__ S) {
    int tid = threadIdx.x;
    int i = blockIdx.x * TPB + tid;
    int w = tid >> 5, lane = tid & 31;

    int s20 = S[i] % 21;
    int nsc = c_nsc[s20], chin = c_chin[s20];

    __shared__ int whist[8][11];
    if (tid < 88) ((int*)whist)[tid] = 0;
    __syncthreads();
    unsigned mmask = __match_any_sync(0xffffffffu, nsc);
    int rank = __popc(mmask & ((1u << lane) - 1u));
    if (rank == 0) whist[w][nsc] = __popc(mmask);
    __syncthreads();
    int wb = 0;
    for (int w2 = 0; w2 < w; w2++) wb += whist[w2][nsc];
    int j = d_bhist[nsc * NBLK + blockIdx.x] + wb + rank;

    d_inv[i] = j;
    d_nsc[j] = nsc;

    // vectorized row load (rows are 8B-aligned: 42 floats = 168 bytes)
    float buf[42];
    const float2* x2 = reinterpret_cast<const float2*>(X + (size_t)i * 42);
#pragma unroll
    for (int q = 0; q < 21; q++) {
        float2 t = x2[q];
        buf[2 * q] = t.x; buf[2 * q + 1] = t.y;
    }
    V3 p[9];
#pragma unroll
    for (int q = 0; q < 9; q++) p[q] = v3(buf[3 * q], buf[3 * q + 1], buf[3 * q + 2]);

    const int Q[4][4] = {{0,1,4,5},{1,4,5,6},{4,5,6,7},{5,6,7,8}};
#pragma unroll
    for (int k = 0; k < 4; k++) {
        float ch = 0.f;
        if (k < chin) ch = dihed(p[Q[k][0]], p[Q[k][1]], p[Q[k][2]], p[Q[k][3]]);
        d_chi[k * NRES + j] = ch;                     // buffer 0 (chi(0))
        d_chi[1 * 4 * NRES + k * NRES + j] = ch;      // buffer 1
        d_chi[2 * 4 * NRES + k * NRES + j] = ch;      // buffer 2
    }

    V3 cb = extendp(p[0], p[2], p[1], cosf(-2.14f), sinf(-2.14f));
    V3 vv = cb - p[1]; float nv = sqrtf(dot3(vv, vv)); V3 u = vv * (1.f / (nv + 1e-8f));
    V3 ww = p[1] - p[0]; V3 pp = crs3(ww, u); float np = sqrtf(dot3(pp, pp)); V3 nn = pp * (1.f / (np + 1e-8f));
    V3 mm = crs3(nn, u);
    stpre(0, j, p[1]); stpre(1, j, cb); stpre(2, j, u); stpre(3, j, nn); stpre(4, j, mm);

#pragma unroll
    for (int s = 0; s < 10; s++) {
#pragma unroll
        for (int q = 0; q < 3; q++) d_tgt[(3 * s + q) * NRES + j] = buf[(4 + s) * 3 + q];
    }
}

// ---------------- persistent optimizer: warp-autonomous, lag-1 speculative ----------------
// 591 compute blocks at 4 CTAs/SM. Warp w owns slice (w + 5*ci) & 7 of the ci-th
// chunk (stride-5 rotation spreads cost-ascending slices across warps; ownership
// static across iterations). Iteration it: read chi(it) from buffer it%3, run
// chain -> gradient in registers, fused Adam (corrections for t=it+1) -> chi(it+1)
// into buffer (it+1)%3. Triple buffering keeps the final chi(st) intact under
// depth-1 speculation. No block barriers; block 591 reduces + decides convergence.
// Chain float path identical to rounds 7/9/10/11; Adam expressions relocated verbatim.
__global__ void __launch_bounds__(TPB, 4) k_opt() {
    const int bid  = blockIdx.x;
    const int tid  = threadIdx.x;
    const int lane = tid & 31;
    const int wrp  = tid >> 5;

    __shared__ double wsum[8];
    __shared__ int s_cnt[2];
    __shared__ int sh_sig;

    if (bid == NCB) {
        // ---------------- reducer block ----------------
        float prevf = 100.0f;
        for (int t = 0; t <= 200; ++t) {
            if (tid == 0) {
                while (atomicAdd(&d_arr[t & 1], 0) < NCB) __nanosleep(128);
                atomicExch(&d_arr[t & 1], 0);   // reuse for t+2 (blocks gated by d_gen)
            }
            __syncthreads();
            __threadfence();
            const double* pp = d_part + (size_t)(t & 1) * NPART;
            double s = 0.0;
            for (int q = tid; q < NPART; q += TPB) s += __ldcg(pp + q);
#pragma unroll
            for (int o = 16; o; o >>= 1) s += __shfl_down_sync(0xffffffffu, s, o);
            if (lane == 0) wsum[wrp] = s;
            __syncthreads();
            if (tid == 0) {
                double tot = 0.0;
#pragma unroll
                for (int q2 = 0; q2 < 8; q2++) tot += wsum[q2];
                float mse = (float)(tot / (3.0 * (double)d_cnt));
                bool stop = (fabsf(mse - prevf) < 1e-4f) || (t >= 200);
                prevf = mse;
                sh_sig = stop ? 1 : 0;
                if (stop) {
                    d_stopT = t;
                    d_finalbuf = t % 3;     // chi(t) lives in buffer t%3
                    __threadfence();
                    atomicExch(&d_gen, 1000);   // release all waiters
                } else {
                    __threadfence();
                    atomicExch(&d_gen, t + 1);  // verdicts 0..t published
                }
            }
            __syncthreads();
            if (sh_sig) break;
        }
        return;
    }

    // ---------------- compute blocks ----------------
    if (tid < 2) s_cnt[tid] = 0;
    __syncthreads();

    const int half = tid & 1;
    const float cA = cosf(1.937f), sA = sinf(1.937f);
    const float COS_PI = cosf(PI_F), SIN_PI = sinf(PI_F);
    const float ivd = d_invden;
    const int nstat = d_nstatic;
    const int ccount = d_scnt[bid];
    const int lslot = (lane >> 1);   // residue slot within a 16-residue slice

    for (int it = 0; it <= 200; ++it) {
        if (it >= 2) {
            int st = 0;
            if (lane == 0) {
                while (*((volatile int*)&d_gen) < it - 1) __nanosleep(128);
                __threadfence();
                st = *(volatile int*)&d_stopT;
            }
            st = __shfl_sync(0xffffffffu, st, 0);
            if (st >= 0 && st < it) break;   // converged at st: chi[st%3] is final
        }
        // bias corrections for the FUSED Adam step (producing chi(it+1), i.e. t = it+1)
        const float b1c = 1.0f - powf(0.9f, (float)(it + 1));
        const float b2c = 1.0f - powf(0.999f, (float)(it + 1));
        const int roff = (it % 3) * 4 * NRES;          // chi(it)
        const int woff = ((it + 1) % 3) * 4 * NRES;    // chi(it+1)
        const int par  = it & 1;

        for (int ci = 0; ci < ccount; ++ci) {
            const int c = d_list[bid * MAXPER + ci];
            if (it > 0 && c < nstat) continue;   // static chunk: partial cached at it=0

            const int slice = (wrp + 5 * ci) & 7;  // stride-5 rotation, iteration-invariant
            const int r = (c << 7) + (slice << 4) + lslot;
            const int nsc = d_nsc[r];
            const int nAct = min(4, max(0, nsc - 1));   // chis with nonzero gradient

            // ---- chi(it): this thread owns chis {2*half, 2*half+1}; dead chis are 0 ----
            const int k0 = half * 2;
            float myc0 = 0.f, myc1 = 0.f;
#pragma unroll
            for (int q = 0; q < 2; q++) {
                if (k0 + q < nAct) {
                    float cc = d_chi[roff + (k0 + q) * NRES + r];
                    if (q == 0) myc0 = cc; else myc1 = cc;
                }
            }
            const float oc0 = __shfl_xor_sync(0xffffffffu, myc0, 1);
            const float oc1 = __shfl_xor_sync(0xffffffffu, myc1, 1);
            float chi[4];
            chi[half * 2]           = myc0;
            chi[half * 2 + 1]       = myc1;
            chi[(1 - half) * 2]     = oc0;
            chi[(1 - half) * 2 + 1] = oc1;

            const unsigned nscmax = __reduce_max_sync(0xffffffffu, (unsigned)nsc);

            float loss = 0.f, g0 = 0.f, g1 = 0.f;

            if (nscmax > 0) {
                V3 cb = ldpre(1, r);
                if (nsc > 0) { V3 df = cb - ldtgt(0, r); loss += dot3(df, df); }

                if (nscmax > 1) {
                    V3 p1 = ldpre(0, r), u1 = ldpre(2, r), n1 = ldpre(3, r), m1 = ldpre(4, r);
                    float s0, c0; sincosf(chi[0], &s0, &c0);
                    V3 A5 = cb + (u1 * (-cA) + (m1 * c0 + n1 * s0) * sA) * BLEN;
                    V3 t5 = (n1 * c0 - m1 * s0) * (sA * BLEN);
                    if (nsc > 1) {
                        V3 df = A5 - ldtgt(1, r);
                        loss += dot3(df, df);
                        if (half == 0) g0 += 2.f * dot3(df, t5);
                    }

                    V3 a = p1, b = cb, c2 = A5;
                    V3 at[2], bt[2], ct[2];
#pragma unroll
                    for (int q = 0; q < 2; q++) { at[q] = v3(0,0,0); bt[q] = v3(0,0,0); ct[q] = v3(0,0,0); }
                    if (half == 0) ct[0] = t5;

#pragma unroll
                    for (int s = 2; s < 10; s++) {
                        if ((unsigned)s >= nscmax) break;   // warp-uniform after sort
                        float cT, sT; int ka;
                        if (s <= 4) { sincosf(chi[s - 1], &sT, &cT); ka = s - 1; }
                        else        { cT = COS_PI; sT = SIN_PI; ka = -1; }

                        // EXACT round-3 arithmetic (trajectory-critical)
                        V3 v = c2 - b;
                        float nv = sqrtf(dot3(v, v));
                        float iv = 1.f / (nv + 1e-8f);
                        float rnv = 1.f / nv;
                        V3 u = v * iv;
                        V3 w = b - a;
                        V3 pp = crs3(w, u);
                        float np = sqrtf(dot3(pp, pp));
                        float ip = 1.f / (np + 1e-8f);
                        float rnp = 1.f / np;
                        V3 nn = pp * ip;
                        V3 mm = crs3(nn, u);
                        V3 d = c2 + (u * (-cA) + (mm * cT + nn * sT) * sA) * BLEN;

                        V3 dt[2];
#pragma unroll
                        for (int q = 0; q < 2; q++) {
                            V3 vd = ct[q] - bt[q];
                            float nvd = dot3(v, vd) * rnv;
                            V3 ud = vd * iv - v * (nvd * iv * iv);
                            V3 wd = bt[q] - at[q];
                            V3 pd = crs3(wd, u) + crs3(w, ud);
                            float npd = dot3(pp, pd) * rnp;
                            V3 nd = pd * ip - pp * (npd * ip * ip);
                            V3 md = crs3(nd, u) + crs3(nn, ud);
                            V3 dd = ct[q] + (ud * (-cA) + (md * cT + nd * sT) * sA) * BLEN;
                            if (half * 2 + q == ka) dd = dd + (nn * cT - mm * sT) * (sA * BLEN);
                            dt[q] = dd;
                        }

                        if (s < nsc) {
                            V3 df = d - ldtgt(s, r);
                            loss += dot3(df, df);
                            g0 += 2.f * dot3(df, dt[0]);
                            g1 += 2.f * dot3(df, dt[1]);
                        }
                        a = b; b = c2; c2 = d;
#pragma unroll
                        for (int q = 0; q < 2; q++) { at[q] = bt[q]; bt[q] = ct[q]; ct[q] = dt[q]; }
                    }
                }
            }

            // ---- fused Adam: produce chi(it+1) in buffer (it+1)%3 (live chis only) ----
#pragma unroll
            for (int q = 0; q < 2; q++) {
                if (k0 + q < nAct) {
                    const int idx = (k0 + q) * NRES + r;
                    float g = (q == 0 ? g0 : g1) * ivd;
                    float m, v;
                    if (it == 0) {
                        // bitwise-equal to the m=v=0 forms below
                        m = 0.1f * g;
                        v = (0.001f * g) * g;
                    } else {
                        m = 0.9f * d_m[idx] + 0.1f * g;
                        v = 0.999f * d_v[idx] + 0.001f * g * g;
                    }
                    d_m[idx] = m; d_v[idx] = v;
                    float mh = m / b1c, vh = v / b2c;
                    float cc = (q == 0 ? myc0 : myc1) - mh / (sqrtf(vh) + 1e-8f);
                    d_chi[woff + idx] = cc;
                }
            }

            // per-(chunk,slice) loss partial (both halves identical primal loss -> x0.5 exact)
            double val = (double)loss;
#pragma unroll
            for (int o = 16; o; o >>= 1) val += __shfl_down_sync(0xffffffffu, val, o);
            if (lane == 0) {
                val *= 0.5;
                d_part[(size_t)par * NPART + (c << 3) + slice] = val;
                if (it == 0 && c < nstat) d_part[(size_t)NPART + (c << 3) + slice] = val;  // cache both parities
            }
        }

        // per-block arrival: 8th warp posts the global arrival (no block barrier)
        if (lane == 0) {
            __threadfence();
            int old = atomicAdd(&s_cnt[par], 1);
            if (old == 7) {
                atomicExch(&s_cnt[par], 0);
                __threadfence();
                atomicAdd(&d_arr[par], 1);
            }
        }
    }
}

__global__ void k_final(const float* __restrict__ X, float* __restrict__ out) {
    int i = blockIdx.x * TPB + threadIdx.x;
    int j = d_inv[i];
    const int fb = d_finalbuf * 4 * NRES;
    const float cA = cosf(1.937f), sA = sinf(1.937f);
    const float* xr = X + (size_t)i * 42;
    float* o = out + (size_t)i * 42;

    // vectorized backbone passthrough (rows 8B-aligned)
    const float2* x2 = reinterpret_cast<const float2*>(xr);
    float2* o2 = reinterpret_cast<float2*>(o);
#pragma unroll
    for (int q = 0; q < 6; q++) o2[q] = x2[q];

    float chi[4];
#pragma unroll
    for (int k = 0; k < 4; k++) chi[k] = d_chi[fb + k * NRES + j];

    V3 p1 = ldpre(0, j), cb = ldpre(1, j), u1 = ldpre(2, j), n1 = ldpre(3, j), m1 = ldpre(4, j);
    V3 atoms[10];
    atoms[0] = cb;
    float c0 = cosf(chi[0]), s0 = sinf(chi[0]);
    V3 A5 = cb + (u1 * (-cA) + (m1 * c0 + n1 * s0) * sA) * BLEN;
    atoms[1] = A5;
    V3 a = p1, b = cb, c = A5;
#pragma unroll
    for (int s = 2; s < 10; s++) {
        float cT, sT;
        if (s <= 4) { float T = chi[s - 1]; cT = cosf(T); sT = sinf(T); }
        else        { cT = cosf(PI_F); sT = sinf(PI_F); }
        V3 d = extendp(a, b, c, cT, sT);
        atoms[s] = d;
        a = b; b = c; c = d;
    }
    float sc[30];
#pragma unroll
    for (int s = 0; s < 10; s++) {
        sc[3 * s + 0] = atoms[s].x;
        sc[3 * s + 1] = atoms[s].y;
        sc[3 * s + 2] = atoms[s].z;
    }
    float2* os = o2 + 6;   // offset 12 floats (even) -> aligned
#pragma unroll
    for (int q = 0; q < 15; q++) os[q] = make_float2(sc[2 * q], sc[2 * q + 1]);
}

// ---------------- launch ----------------
extern "C" void kernel_launch(void* const* d_in, const int* in_sizes, int n_in,
                              void* d_out, int out_size) {
    const float* X = (const float*)d_in[0];
    const int*   S = (const int*)d_in[1];
    // d_in[2] = batch_ids: contiguous equal segments -> pure reshape, unused.
    float* out = (float*)d_out;

    k_hist<<<NBLK, TPB>>>(S);
    k_scan<<<1, 352>>>();
    k_sched<<<(NCHUNK + 255) / 256, 256>>>();
    k_scatter<<<NBLK, TPB>>>(X, S);
    k_opt<<<PGRID, TPB>>>();
    k_final<<<NBLK, TPB>>>(X, out);
}

// round 16
// speedup vs baseline: 1.0229x; 1.0229x over previous
#include <cuda_runtime.h>
#include <math.h>

// Problem dims (fixed by reference: B=1024, L=256)
#define NRES   262144
#define TPB    256
#define NBLK   (NRES / TPB)    // 1024
#define NCHUNK (NRES / 128)    // 2048 chunks of 128 residues (2 threads each)
#define NPART  (NCHUNK * 8)    // per-(chunk,slice) partials
#define NCB    591             // compute blocks; block NCB is the dedicated reducer
#define PGRID  (NCB + 1)       // 592 = 148 SMs * 4 CTAs -> all resident
#define MAXPER 16              // max chunks per block in the schedule
#define BLEN   1.52f
#define PI_F   3.14159265358979323846f

// ---------------- small vec helpers ----------------
struct V3 { float x, y, z; };
__device__ __forceinline__ V3 v3(float a, float b, float c) { V3 r; r.x = a; r.y = b; r.z = c; return r; }
__device__ __forceinline__ V3 operator+(V3 a, V3 b) { return v3(a.x + b.x, a.y + b.y, a.z + b.z); }
__device__ __forceinline__ V3 operator-(V3 a, V3 b) { return v3(a.x - b.x, a.y - b.y, a.z - b.z); }
__device__ __forceinline__ V3 operator*(V3 a, float s) { return v3(a.x * s, a.y * s, a.z * s); }
__device__ __forceinline__ float dot3(V3 a, V3 b) { return a.x * b.x + a.y * b.y + a.z * b.z; }
__device__ __forceinline__ V3 crs3(V3 a, V3 b) {
    return v3(a.y * b.z - a.z * b.y, a.z * b.x - a.x * b.z, a.x * b.y - a.y * b.x);
}

// ---------------- residue-type tables ----------------
__constant__ int c_nsc[21]  = {1,7,4,4,2,5,5,0,6,4,4,5,4,7,3,2,3,10,8,3,0};
__constant__ int c_chin[21] = {0,4,2,2,1,3,3,0,2,2,2,4,3,2,2,1,1,2,2,1,0};

// ---------------- device state (static; no runtime alloc) ----------------
__device__ float  d_chi[2 * 4 * NRES];   // double-buffered chi (lag-1 speculation rollback)
__device__ float  d_m  [4 * NRES];
__device__ float  d_v  [4 * NRES];
__device__ float  d_g  [4 * NRES];
__device__ float  d_pre[15 * NRES];      // SoA: p1, CB, u1, n1, m1
__device__ float  d_tgt[30 * NRES];      // SoA sidechain targets
__device__ int    d_nsc[NRES];
__device__ int    d_inv[NRES];           // original i -> sorted j
__device__ int    d_bhist[11 * NBLK];
__device__ double d_part[2 * NPART];     // per-(chunk,slice) loss partials, by parity
__device__ int    d_arr[2];              // arrival counters, by parity
__device__ int    d_gen, d_stopT, d_finalbuf, d_cnt, d_nstatic;
__device__ float  d_invden;
__device__ int    d_assign[NCHUNK];      // chunk -> compute block
__device__ int    d_scnt[NCB];           // per-block chunk counts
__device__ int    d_list[NCB * MAXPER];  // per-block chunk lists

__device__ __forceinline__ V3 ldpre(int c, int j) {
    return v3(d_pre[(3 * c + 0) * NRES + j], d_pre[(3 * c + 1) * NRES + j], d_pre[(3 * c + 2) * NRES + j]);
}
__device__ __forceinline__ void stpre(int c, int j, V3 a) {
    d_pre[(3 * c + 0) * NRES + j] = a.x;
    d_pre[(3 * c + 1) * NRES + j] = a.y;
    d_pre[(3 * c + 2) * NRES + j] = a.z;
}
__device__ __forceinline__ V3 ldtgt(int s, int j) {
    return v3(d_tgt[(3 * s + 0) * NRES + j], d_tgt[(3 * s + 1) * NRES + j], d_tgt[(3 * s + 2) * NRES + j]);
}

// NeRF extend, primal only
__device__ __forceinline__ V3 extendp(V3 a, V3 b, V3 c, float cT, float sT) {
    const float cA = cosf(1.937f), sA = sinf(1.937f);
    V3 v = c - b; float nv = sqrtf(dot3(v, v)); V3 u = v * (1.f / (nv + 1e-8f));
    V3 w = b - a; V3 pp = crs3(w, u); float np = sqrtf(dot3(pp, pp)); V3 nn = pp * (1.f / (np + 1e-8f));
    V3 mm = crs3(nn, u);
    return c + (u * (-cA) + (mm * cT + nn * sT) * sA) * BLEN;
}

__device__ __forceinline__ float dihed(V3 a, V3 b, V3 c, V3 d) {
    V3 b1 = b - a, b2 = c - b, b3 = d - c;
    V3 n1 = crs3(b1, b2), n2 = crs3(b2, b3);
    float nb = sqrtf(dot3(b2, b2));
    V3 u2 = b2 * (1.f / (nb + 1e-8f));
    V3 m1 = crs3(n1, u2);
    return atan2f(dot3(m1, n2), dot3(n1, n2));
}

// ---------------- counting sort by n_sc (deterministic / stable) ----------------
__global__ void k_hist(const int* __restrict__ S) {
    __shared__ int h[11];
    int tid = threadIdx.x;
    if (tid < 11) h[tid] = 0;
    __syncthreads();
    int i = blockIdx.x * TPB + tid;
    int nsc = c_nsc[S[i] % 21];
    atomicAdd(&h[nsc], 1);
    __syncthreads();
    if (tid < 11) d_bhist[tid * NBLK + blockIdx.x] = h[tid];
}

// scan + control-state init + chunk->block schedule (snake rows 0-2, LPT tail).
// 352 threads = 11 warps (one per nsc class).
__global__ void k_scan() {
    __shared__ int tot[11], base[11], cbase[12];
    __shared__ int W[NCHUNK];       // per-chunk relative cost
    __shared__ int load[NCB];
    __shared__ int nstat_s;
    const int tid = threadIdx.x;
    const int wv = tid >> 5, lane = tid & 31;

    int lsum = 0;
    if (wv < 11) {
        for (int j = 0; j < 32; j++) lsum += d_bhist[wv * NBLK + lane * 32 + j];
        int isum = lsum;
        for (int o = 1; o < 32; o <<= 1) {
            int t = __shfl_up_sync(0xffffffffu, isum, o);
            if (lane >= o) isum += t;
        }
        if (lane == 31) tot[wv] = isum;
    }
    __syncthreads();

    if (tid == 0) {
        int o = 0, cnt = 0;
        for (int u = 0; u < 11; u++) { base[u] = o; cbase[u] = o; o += tot[u]; cnt += u * tot[u]; }
        cbase[11] = NRES;
        d_cnt = cnt;
        d_invden = 1.0f / (3.0f * (float)cnt);
        d_gen = 0; d_stopT = -1; d_finalbuf = 0;
        d_arr[0] = 0; d_arr[1] = 0;
        int nst = (tot[0] + tot[1]) >> 7;   // chunks wholly of nsc<=1 residues
        d_nstatic = nst;
        nstat_s = nst;
    }
    __syncthreads();

    // rewrite d_bhist to per-block scatter offsets (warp-parallel prefix per class)
    if (wv < 11) {
        int excl = lsum;
        for (int o = 1; o < 32; o <<= 1) {
            int t = __shfl_up_sync(0xffffffffu, excl, o);
            if (lane >= o) excl += t;
        }
        excl -= lsum;   // exclusive
        int off = base[wv] + excl;
        for (int j = 0; j < 32; j++) {
            int idx = wv * NBLK + lane * 32 + j;
            int t = d_bhist[idx];
            d_bhist[idx] = off;
            off += t;
        }
    }

    // per-chunk cost: sum over the chunk's 8 slices of (4 + 3*chain_steps(slice-max class)).
    for (int c = tid; c < NCHUNK; c += 352) {
        int wsum = 0;
        for (int w = 0; w < 8; w++) {
            int j = (c << 7) + (w << 4) + 15;   // last (max-class) residue of this slice
            int u = 0;
            for (int q = 1; q < 11; q++) if (j >= cbase[q]) u = q;
            int steps = u > 2 ? (u - 2) : 0;
            wsum += 4 + 3 * steps;
        }
        if (c < nstat_s) wsum = 2;   // static chunk: skipped after it=0
        W[c] = wsum;
    }
    for (int c = tid; c < 3 * NCB; c += 352) {
        int r = c / NCB, col = c % NCB;
        d_assign[c] = (r & 1) ? (NCB - 1 - col) : col;
    }
    for (int b = tid; b < NCB; b += 352) d_scnt[b] = 0;
    __syncthreads();
    for (int b = tid; b < NCB; b += 352)
        load[b] = W[b] + W[2 * NCB - 1 - b] + W[2 * NCB + b];
    __syncthreads();

    // LPT greedy for the expensive tail chunks (descending cost order)
    if (wv == 0) {
        for (int c = NCHUNK - 1; c >= 3 * NCB; --c) {
            int best = 0x7fffffff;
            for (int b = lane; b < NCB; b += 32) {
                int v = load[b] * 1024 + b;     // tie-break: lowest block id
                if (v < best) best = v;
            }
#pragma unroll
            for (int o = 16; o; o >>= 1) {
                int t = __shfl_xor_sync(0xffffffffu, best, o);
                if (t < best) best = t;
            }
            int bmin = best & 1023;
            if (lane == 0) { load[bmin] += W[c]; d_assign[c] = bmin; }
            __syncwarp();
        }
    }
}

// materialize per-block chunk lists (order within block irrelevant: per-chunk
// partials and per-residue state are chunk-owned, nothing accumulates across chunks)
__global__ void k_sched() {
    int c = blockIdx.x * 256 + threadIdx.x;
    if (c < NCHUNK) {
        int a = d_assign[c];
        int pos = atomicAdd(&d_scnt[a], 1);
        d_list[a * MAXPER + pos] = c;
    }
}

// scatter + per-residue precompute, stored at sorted position j
__global__ void k_scatter(const float* __restrict__ X, const int* __restrict__ S) {
    int tid = threadIdx.x;
    int i = blockIdx.x * TPB + tid;
    int w = tid >> 5, lane = tid & 31;

    int s20 = S[i] % 21;
    int nsc = c_nsc[s20], chin = c_chin[s20];

    __shared__ int whist[8][11];
    if (tid < 88) ((int*)whist)[tid] = 0;
    __syncthreads();
    unsigned mmask = __match_any_sync(0xffffffffu, nsc);
    int rank = __popc(mmask & ((1u << lane) - 1u));
    if (rank == 0) whist[w][nsc] = __popc(mmask);
    __syncthreads();
    int wb = 0;
    for (int w2 = 0; w2 < w; w2++) wb += whist[w2][nsc];
    int j = d_bhist[nsc * NBLK + blockIdx.x] + wb + rank;

    d_inv[i] = j;
    d_nsc[j] = nsc;

    // vectorized row load (rows are 8B-aligned: 42 floats = 168 bytes)
    float buf[42];
    const float2* x2 = reinterpret_cast<const float2*>(X + (size_t)i * 42);
#pragma unroll
    for (int q = 0; q < 21; q++) {
        float2 t = x2[q];
        buf[2 * q] = t.x; buf[2 * q + 1] = t.y;
    }
    V3 p[9];
#pragma unroll
    for (int q = 0; q < 9; q++) p[q] = v3(buf[3 * q], buf[3 * q + 1], buf[3 * q + 2]);

    const int Q[4][4] = {{0,1,4,5},{1,4,5,6},{4,5,6,7},{5,6,7,8}};
#pragma unroll
    for (int k = 0; k < 4; k++) {
        float ch = 0.f;
        if (k < chin) ch = dihed(p[Q[k][0]], p[Q[k][1]], p[Q[k][2]], p[Q[k][3]]);
        d_chi[k * NRES + j] = ch;                 // buffer 0
        d_chi[4 * NRES + k * NRES + j] = ch;      // buffer 1
        d_m[k * NRES + j] = 0.f;
        d_v[k * NRES + j] = 0.f;
    }

    V3 cb = extendp(p[0], p[2], p[1], cosf(-2.14f), sinf(-2.14f));
    V3 vv = cb - p[1]; float nv = sqrtf(dot3(vv, vv)); V3 u = vv * (1.f / (nv + 1e-8f));
    V3 ww = p[1] - p[0]; V3 pp = crs3(ww, u); float np = sqrtf(dot3(pp, pp)); V3 nn = pp * (1.f / (np + 1e-8f));
    V3 mm = crs3(nn, u);
    stpre(0, j, p[1]); stpre(1, j, cb); stpre(2, j, u); stpre(3, j, nn); stpre(4, j, mm);

#pragma unroll
    for (int s = 0; s < 10; s++) {
#pragma unroll
        for (int q = 0; q < 3; q++) d_tgt[(3 * s + q) * NRES + j] = buf[(4 + s) * 3 + q];
    }
}

// ---------------- persistent optimizer: warp-autonomous, lag-1 speculative ----------------
// Round-11 champion configuration. Warp w owns slice (w + 5*ci) & 7 of the ci-th
// chunk in the block's LPT list (stride-5 rotation: spreads the cost-ascending
// slice axis evenly across warps; ownership still static across iterations, so
// every g/m/v element is produced and consumed by the same thread). No block
// barriers. Block 591 only reduces + decides convergence. Verdict gating via
// plain volatile loads. Float path identical to rounds 7/9/10/11.
__global__ void __launch_bounds__(TPB, 4) k_opt() {
    const int bid  = blockIdx.x;
    const int tid  = threadIdx.x;
    const int lane = tid & 31;
    const int wrp  = tid >> 5;

    __shared__ double wsum[8];
    __shared__ int s_cnt[2];
    __shared__ int sh_sig;

    if (bid == NCB) {
        // ---------------- reducer block ----------------
        float prevf = 100.0f;
        for (int t = 0; t <= 200; ++t) {
            if (tid == 0) {
                while (atomicAdd(&d_arr[t & 1], 0) < NCB) __nanosleep(128);
                atomicExch(&d_arr[t & 1], 0);   // reuse for t+2 (blocks gated by d_gen)
            }
            __syncthreads();
            __threadfence();
            const double* pp = d_part + (size_t)(t & 1) * NPART;
            double s = 0.0;
            for (int q = tid; q < NPART; q += TPB) s += *((volatile const double*)(pp + q));
#pragma unroll
            for (int o = 16; o; o >>= 1) s += __shfl_down_sync(0xffffffffu, s, o);
            if (lane == 0) wsum[wrp] = s;
            __syncthreads();
            if (tid == 0) {
                double tot = 0.0;
#pragma unroll
                for (int q2 = 0; q2 < 8; q2++) tot += wsum[q2];
                float mse = (float)(tot / (3.0 * (double)d_cnt));
                bool stop = (fabsf(mse - prevf) < 1e-4f) || (t >= 200);
                prevf = mse;
                sh_sig = stop ? 1 : 0;
                if (stop) {
                    d_stopT = t;
                    d_finalbuf = t & 1;
                    __threadfence();
                    atomicExch(&d_gen, 1000);   // release all waiters
                } else {
                    __threadfence();
                    atomicExch(&d_gen, t + 1);  // verdicts 0..t published
                }
            }
            __syncthreads();
            if (sh_sig) break;
        }
        return;
    }

    // ---------------- compute blocks ----------------
    if (tid < 2) s_cnt[tid] = 0;
    __syncthreads();

    const int half = tid & 1;
    const float cA = cosf(1.937f), sA = sinf(1.937f);
    const float COS_PI = cosf(PI_F), SIN_PI = sinf(PI_F);
    const float ivd = d_invden;
    const int nstat = d_nstatic;
    const int ccount = d_scnt[bid];
    const int lslot = (lane >> 1);   // residue slot within a 16-residue slice

    for (int it = 0; it <= 200; ++it) {
        if (it >= 2) {
            int st = 0;
            if (lane == 0) {
                while (*((volatile int*)&d_gen) < it - 1) __nanosleep(128);
                __threadfence();
                st = *(volatile int*)&d_stopT;
            }
            st = __shfl_sync(0xffffffffu, st, 0);
            if (st >= 0 && st < it) break;   // converged at st: chi[st&1] is final
        }
        const bool step = (it > 0);
        const float b1c = 1.0f - powf(0.9f, (float)it);
        const float b2c = 1.0f - powf(0.999f, (float)it);
        const int rsel = (it == 0) ? 0 : ((it - 1) & 1);
        const int roff = rsel * 4 * NRES;
        const int woff = (it & 1) * 4 * NRES;
        const int par  = it & 1;

        for (int ci = 0; ci < ccount; ++ci) {
            const int c = d_list[bid * MAXPER + ci];
            if (it > 0 && c < nstat) continue;   // static chunk: partial cached at it=0

            const int slice = (wrp + 5 * ci) & 7;  // stride-5 rotation, iteration-invariant
            const int r = (c << 7) + (slice << 4) + lslot;
            const int nsc = d_nsc[r];
            const int nAct = min(4, max(0, nsc - 1));   // chis with nonzero gradient

            // ---- chi: this thread owns chis {2*half, 2*half+1}; dead chis skipped ----
            float myc0 = 0.f, myc1 = 0.f;
            {
                const int k0 = half * 2;
                if (step) {
#pragma unroll
                    for (int q = 0; q < 2; q++) {
                        if (k0 + q < nAct) {
                            const int idx = (k0 + q) * NRES + r;
                            float g = d_g[idx];
                            float m = 0.9f * d_m[idx] + 0.1f * g;
                            float v = 0.999f * d_v[idx] + 0.001f * g * g;
                            d_m[idx] = m; d_v[idx] = v;
                            float mh = m / b1c, vh = v / b2c;
                            float cc = d_chi[roff + idx] - mh / (sqrtf(vh) + 1e-8f);
                            d_chi[woff + idx] = cc;
                            if (q == 0) myc0 = cc; else myc1 = cc;
                        }
                    }
                } else {
#pragma unroll
                    for (int q = 0; q < 2; q++) {
                        if (k0 + q < nAct) {
                            float cc = d_chi[(k0 + q) * NRES + r];
                            if (q == 0) myc0 = cc; else myc1 = cc;
                        }
                    }
                }
            }
            const float oc0 = __shfl_xor_sync(0xffffffffu, myc0, 1);
            const float oc1 = __shfl_xor_sync(0xffffffffu, myc1, 1);
            float chi[4];
            chi[half * 2]           = myc0;
            chi[half * 2 + 1]       = myc1;
            chi[(1 - half) * 2]     = oc0;
            chi[(1 - half) * 2 + 1] = oc1;

            const unsigned nscmax = __reduce_max_sync(0xffffffffu, (unsigned)nsc);

            float loss = 0.f, g0 = 0.f, g1 = 0.f;

            if (nscmax > 0) {
                V3 cb = ldpre(1, r);
                if (nsc > 0) { V3 df = cb - ldtgt(0, r); loss += dot3(df, df); }

                if (nscmax > 1) {
                    V3 p1 = ldpre(0, r), u1 = ldpre(2, r), n1 = ldpre(3, r), m1 = ldpre(4, r);
                    float s0, c0; sincosf(chi[0], &s0, &c0);
                    V3 A5 = cb + (u1 * (-cA) + (m1 * c0 + n1 * s0) * sA) * BLEN;
                    V3 t5 = (n1 * c0 - m1 * s0) * (sA * BLEN);
                    if (nsc > 1) {
                        V3 df = A5 - ldtgt(1, r);
                        loss += dot3(df, df);
                        if (half == 0) g0 += 2.f * dot3(df, t5);
                    }

                    V3 a = p1, b = cb, c2 = A5;
                    V3 at[2], bt[2], ct[2];
#pragma unroll
                    for (int q = 0; q < 2; q++) { at[q] = v3(0,0,0); bt[q] = v3(0,0,0); ct[q] = v3(0,0,0); }
                    if (half == 0) ct[0] = t5;

#pragma unroll
                    for (int s = 2; s < 10; s++) {
                        if ((unsigned)s >= nscmax) break;   // warp-uniform after sort
                        float cT, sT; int ka;
                        if (s <= 4) { sincosf(chi[s - 1], &sT, &cT); ka = s - 1; }
                        else        { cT = COS_PI; sT = SIN_PI; ka = -1; }

                        // EXACT round-3 arithmetic (trajectory-critical)
                        V3 v = c2 - b;
                        float nv = sqrtf(dot3(v, v));
                        float iv = 1.f / (nv + 1e-8f);
                        float rnv = 1.f / nv;
                        V3 u = v * iv;
                        V3 w = b - a;
                        V3 pp = crs3(w, u);
                        float np = sqrtf(dot3(pp, pp));
                        float ip = 1.f / (np + 1e-8f);
                        float rnp = 1.f / np;
                        V3 nn = pp * ip;
                        V3 mm = crs3(nn, u);
                        V3 d = c2 + (u * (-cA) + (mm * cT + nn * sT) * sA) * BLEN;

                        V3 dt[2];
#pragma unroll
                        for (int q = 0; q < 2; q++) {
                            V3 vd = ct[q] - bt[q];
                            float nvd = dot3(v, vd) * rnv;
                            V3 ud = vd * iv - v * (nvd * iv * iv);
                            V3 wd = bt[q] - at[q];
                            V3 pd = crs3(wd, u) + crs3(w, ud);
                            float npd = dot3(pp, pd) * rnp;
                            V3 nd = pd * ip - pp * (npd * ip * ip);
                            V3 md = crs3(nd, u) + crs3(nn, ud);
                            V3 dd = ct[q] + (ud * (-cA) + (md * cT + nd * sT) * sA) * BLEN;
                            if (half * 2 + q == ka) dd = dd + (nn * cT - mm * sT) * (sA * BLEN);
                            dt[q] = dd;
                        }

                        if (s < nsc) {
                            V3 df = d - ldtgt(s, r);
                            loss += dot3(df, df);
                            g0 += 2.f * dot3(df, dt[0]);
                            g1 += 2.f * dot3(df, dt[1]);
                        }
                        a = b; b = c2; c2 = d;
#pragma unroll
                        for (int q = 0; q < 2; q++) { at[q] = bt[q]; bt[q] = ct[q]; ct[q] = dt[q]; }
                    }
                }
            }

            // store gradients only for live chis
            {
                const int k0 = half * 2;
                if (k0 + 0 < nAct) d_g[(k0 + 0) * NRES + r] = g0 * ivd;
                if (k0 + 1 < nAct) d_g[(k0 + 1) * NRES + r] = g1 * ivd;
            }

            // per-(chunk,slice) loss partial (both halves identical primal loss -> x0.5 exact)
            double val = (double)loss;
#pragma unroll
            for (int o = 16; o; o >>= 1) val += __shfl_down_sync(0xffffffffu, val, o);
            if (lane == 0) {
                val *= 0.5;
                d_part[(size_t)par * NPART + (c << 3) + slice] = val;
                if (it == 0 && c < nstat) d_part[(size_t)NPART + (c << 3) + slice] = val;  // cache both parities
            }
        }

        // per-block arrival: 8th warp posts the global arrival (no block barrier)
        if (lane == 0) {
            __threadfence();
            int old = atomicAdd(&s_cnt[par], 1);
            if (old == 7) {
                atomicExch(&s_cnt[par], 0);
                __threadfence();
                atomicAdd(&d_arr[par], 1);
            }
        }
    }
}

__global__ void k_final(const float* __restrict__ X, float* __restrict__ out) {
    int i = blockIdx.x * TPB + threadIdx.x;
    int j = d_inv[i];
    const int fb = d_finalbuf * 4 * NRES;
    const float cA = cosf(1.937f), sA = sinf(1.937f);
    const float* xr = X + (size_t)i * 42;
    float* o = out + (size_t)i * 42;

    // vectorized backbone passthrough (rows 8B-aligned)
    const float2* x2 = reinterpret_cast<const float2*>(xr);
    float2* o2 = reinterpret_cast<float2*>(o);
#pragma unroll
    for (int q = 0; q < 6; q++) o2[q] = x2[q];

    float chi[4];
#pragma unroll
    for (int k = 0; k < 4; k++) chi[k] = d_chi[fb + k * NRES + j];

    V3 p1 = ldpre(0, j), cb = ldpre(1, j), u1 = ldpre(2, j), n1 = ldpre(3, j), m1 = ldpre(4, j);
    V3 atoms[10];
    atoms[0] = cb;
    float c0 = cosf(chi[0]), s0 = sinf(chi[0]);
    V3 A5 = cb + (u1 * (-cA) + (m1 * c0 + n1 * s0) * sA) * BLEN;
    atoms[1] = A5;
    V3 a = p1, b = cb, c = A5;
#pragma unroll
    for (int s = 2; s < 10; s++) {
        float cT, sT;
        if (s <= 4) { float T = chi[s - 1]; cT = cosf(T); sT = sinf(T); }
        else        { cT = cosf(PI_F); sT = sinf(PI_F); }
        V3 d = extendp(a, b, c, cT, sT);
        atoms[s] = d;
        a = b; b = c; c = d;
    }
    float sc[30];
#pragma unroll
    for (int s = 0; s < 10; s++) {
        sc[3 * s + 0] = atoms[s].x;
        sc[3 * s + 1] = atoms[s].y;
        sc[3 * s + 2] = atoms[s].z;
    }
    float2* os = o2 + 6;   // offset 12 floats (even) -> aligned
#pragma unroll
    for (int q = 0; q < 15; q++) os[q] = make_float2(sc[2 * q], sc[2 * q + 1]);
}

// ---------------- launch ----------------
extern "C" void kernel_launch(void* const* d_in, const int* in_sizes, int n_in,
                              void* d_out, int out_size) {
    const float* X = (const float*)d_in[0];
    const int*   S = (const int*)d_in[1];
    // d_in[2] = batch_ids: contiguous equal segments -> pure reshape, unused.
    float* out = (float*)d_out;

    k_hist<<<NBLK, TPB>>>(S);
    k_scan<<<1, 352>>>();
    k_sched<<<(NCHUNK + 255) / 256, 256>>>();
    k_scatter<<<NBLK, TPB>>>(X, S);
    k_opt<<<PGRID, TPB>>>();
    k_final<<<NBLK, TPB>>>(X, out);
}